// round 16
// baseline (speedup 1.0000x reference)
#include <cuda_runtime.h>
#include <cuda_fp16.h>
#include <cstdint>

#define B_ 4
#define H_ 16
#define T_ 2048
#define K_ 64
#define CH_ 128
#define N_ 16
#define BH_ (B_*H_)
#define OUT_ELEMS (B_*H_*T_*K_)
#define LOGMIN (-5.2983174324035645f)

// ---- scratch ----
__device__ __half g_rwi[B_*H_*T_*K_];     // r * exp(cum_prev)  (fp16)
__device__ __half g_intra[B_*H_*T_*K_];   // intra-chunk out (fp16)
__device__ float g_wkv[BH_*N_*K_*K_];
__device__ float g_wse[BH_*N_*K_];

// ---- phase1 smem layout (float offsets) ----
#define O_RW    0        // 128 x 68 (8704); later partial buffers
#define O_CUM   8704     // 128 x 64 (8192)
#define O_KK    16896    // 128 x 76 (9728) tf32 kk (MMA1 only)
#define O_V     26624    // 128 x 72 (9216) fp32 V (epilogue diag)
#define O_U     35840
#define O_DIAG  35904    // 128
#define O_EWS   36032    // 64
#define O_SEG   36096    // 8 x 64
#define O_VH    36608    // fp16 V: 128 x 72 halves (4608 floats)
#define O_KW    41216    // fp16 kw: 128 x 72 halves (4608 floats)
#define SMEM1_FLOATS 45824
#define SMEM1_BYTES  (SMEM1_FLOATS*4)

__device__ __forceinline__ float f2tf(float x) {
    uint32_t r;
    asm("cvt.rna.tf32.f32 %0, %1;" : "=r"(r) : "f"(x));
    return __uint_as_float(r);
}
__device__ __forceinline__ uint32_t packh2(float a, float b) {
    __half2 h = __floats2half2_rn(a, b);
    return *(uint32_t*)&h;
}
__device__ __forceinline__ void mma1688(float* c, uint32_t a0, uint32_t a1, uint32_t a2, uint32_t a3,
                                        uint32_t b0, uint32_t b1) {
    asm volatile("mma.sync.aligned.m16n8k8.row.col.f32.tf32.tf32.f32 "
                 "{%0,%1,%2,%3},{%4,%5,%6,%7},{%8,%9},{%0,%1,%2,%3};"
                 : "+f"(c[0]), "+f"(c[1]), "+f"(c[2]), "+f"(c[3])
                 : "r"(a0), "r"(a1), "r"(a2), "r"(a3), "r"(b0), "r"(b1));
}
__device__ __forceinline__ void mma16816h(float* c, uint32_t a0, uint32_t a1, uint32_t a2, uint32_t a3,
                                          uint32_t b0, uint32_t b1) {
    asm volatile("mma.sync.aligned.m16n8k16.row.col.f32.f16.f16.f32 "
                 "{%0,%1,%2,%3},{%4,%5,%6,%7},{%8,%9},{%0,%1,%2,%3};"
                 : "+f"(c[0]), "+f"(c[1]), "+f"(c[2]), "+f"(c[3])
                 : "r"(a0), "r"(a1), "r"(a2), "r"(a3), "r"(b0), "r"(b1));
}
__device__ __forceinline__ void ldmx2t(uint32_t& b0, uint32_t& b1, uint32_t addr) {
    asm volatile("ldmatrix.sync.aligned.m8n8.x2.trans.shared.b16 {%0,%1}, [%2];"
                 : "=r"(b0), "=r"(b1) : "r"(addr));
}
__device__ __forceinline__ void ldmx4t(uint32_t& r0, uint32_t& r1, uint32_t& r2, uint32_t& r3,
                                       uint32_t addr) {
    asm volatile("ldmatrix.sync.aligned.m8n8.x4.trans.shared.b16 {%0,%1,%2,%3}, [%4];"
                 : "=r"(r0), "=r"(r1), "=r"(r2), "=r"(r3) : "r"(addr));
}
#define FB(x) __float_as_uint(x)

__device__ __forceinline__ uint32_t smem_u32(const void* p) {
    uint32_t a;
    asm("{ .reg .u64 t; cvta.to.shared.u64 t, %1; cvt.u32.u64 %0, t; }" : "=r"(a) : "l"(p));
    return a;
}
__device__ __forceinline__ void cp_async16(uint32_t dst, const void* src) {
    asm volatile("cp.async.cg.shared.global [%0], [%1], 16;" :: "r"(dst), "l"(src) : "memory");
}
__device__ __forceinline__ void cp_commit() { asm volatile("cp.async.commit_group;" ::: "memory"); }
__device__ __forceinline__ void cp_wait0()  { asm volatile("cp.async.wait_group 0;" ::: "memory"); }

// ======================= phase 1 =======================
__global__ void __launch_bounds__(512)
rwkv_phase1(const float* __restrict__ r, const float* __restrict__ k,
            const float* __restrict__ v, const float* __restrict__ w,
            const float* __restrict__ u)
{
    extern __shared__ float sm[];
    __half* vh  = (__half*)(sm + O_VH);
    __half* kwh = (__half*)(sm + O_KW);
    const int tid = threadIdx.x;
    const int wid = tid >> 5, lid = tid & 31;
    const int ly = lid >> 2, lx = lid & 3;
    const int bhn = blockIdx.x;
    const int bh = bhn >> 4, n = bhn & 15;
    const int h = bh & (H_ - 1);
    const int base = bh * (T_ * K_) + n * (CH_ * K_);

    float4 pr[4], pk[4];
    {
        const float4* r4g = (const float4*)(r + base);
        const float4* k4g = (const float4*)(k + base);
        #pragma unroll
        for (int it = 0; it < 4; ++it) {
            pr[it] = r4g[tid + it * 512];
            pk[it] = k4g[tid + it * 512];
        }
    }

    {
        const float4* w4 = (const float4*)(w + base);
        const float4* v4 = (const float4*)(v + base);
        #pragma unroll
        for (int it = 0; it < 4; ++it) {
            int f4 = tid + it * 512;
            int t = f4 >> 4, k0 = (f4 & 15) * 4;
            float4 ww = w4[f4];
            ww.x = fmaxf(ww.x, LOGMIN); ww.y = fmaxf(ww.y, LOGMIN);
            ww.z = fmaxf(ww.z, LOGMIN); ww.w = fmaxf(ww.w, LOGMIN);
            *(float4*)&sm[O_CUM + t * 64 + k0] = ww;
            float4 vv = v4[f4];
            vv.x = f2tf(vv.x); vv.y = f2tf(vv.y); vv.z = f2tf(vv.z); vv.w = f2tf(vv.w);
            *(float4*)&sm[O_V + t * 72 + k0] = vv;
            uint2 hp = make_uint2(packh2(vv.x, vv.y), packh2(vv.z, vv.w));
            *(uint2*)&vh[t * 72 + k0] = hp;
        }
        if (tid < 64) sm[O_U + tid] = u[h * 64 + tid];
    }
    __syncthreads();

    {
        int kq = tid & 63, seg = tid >> 6;
        float run = 0.f;
        #pragma unroll
        for (int tt = 0; tt < 16; ++tt) {
            int idx = (seg * 16 + tt) * 64 + kq;
            run += sm[O_CUM + idx];
            sm[O_CUM + idx] = run;
        }
        sm[O_SEG + seg * 64 + kq] = run;
    }
    __syncthreads();

    {
        int kq = tid & 63, seg = tid >> 6;
        if (seg > 0) {
            float pre = 0.f;
            #pragma unroll
            for (int s = 0; s < 7; ++s)
                if (s < seg) pre += sm[O_SEG + s * 64 + kq];
            #pragma unroll
            for (int tt = 0; tt < 16; ++tt) sm[O_CUM + (seg * 16 + tt) * 64 + kq] += pre;
        } else {
            float ws = 0.f;
            #pragma unroll
            for (int s = 0; s < 8; ++s) ws += sm[O_SEG + s * 64 + kq];
            float ews = __expf(ws);
            sm[O_EWS + kq] = ews;
            g_wse[(bh * N_ + n) * K_ + kq] = ews;
        }
    }
    __syncthreads();

    {
        #pragma unroll
        for (int it = 0; it < 4; ++it) {
            int f4 = tid + it * 512;
            int t = f4 >> 4, k0 = (f4 & 15) * 4;
            float4 rv = pr[it];
            float4 kv = pk[it];
            float4 c4 = *(const float4*)&sm[O_CUM + t * 64 + k0];
            float4 cp4 = (t > 0) ? *(const float4*)&sm[O_CUM + (t - 1) * 64 + k0]
                                 : make_float4(0.f, 0.f, 0.f, 0.f);
            float4 uu = *(const float4*)&sm[O_U + k0];
            float4 ew4 = *(const float4*)&sm[O_EWS + k0];
            float re[4] = {rv.x, rv.y, rv.z, rv.w};
            float ke[4] = {kv.x, kv.y, kv.z, kv.w};
            float ce[4] = {c4.x, c4.y, c4.z, c4.w};
            float cpe[4] = {cp4.x, cp4.y, cp4.z, cp4.w};
            float ue[4] = {uu.x, uu.y, uu.z, uu.w};
            float ewe[4] = {ew4.x, ew4.y, ew4.z, ew4.w};
            float rwv[4], kkv[4], kwv[4];
            float dpart = 0.f;
            #pragma unroll
            for (int e = 0; e < 4; ++e) {
                rwv[e] = f2tf(re[e] * __expf(cpe[e]));   // r * exp(cum_prev)
                kkv[e] = f2tf(ke[e] * __expf(-ce[e]));   // k * exp(-cum)
                kwv[e] = kkv[e] * ewe[e];                // k * exp(ws - cum), bounded
                dpart += re[e] * ue[e] * ke[e];
            }
            *(float4*)&sm[O_RW + t * 68 + k0] = make_float4(rwv[0], rwv[1], rwv[2], rwv[3]);
            *(float4*)&sm[O_KK + t * 76 + k0] = make_float4(kkv[0], kkv[1], kkv[2], kkv[3]);
            uint2 kwp = make_uint2(packh2(kwv[0], kwv[1]), packh2(kwv[2], kwv[3]));
            *(uint2*)&kwh[t * 72 + k0] = kwp;
            uint2 hp = make_uint2(packh2(rwv[0], rwv[1]), packh2(rwv[2], rwv[3]));
            *(uint2*)&g_rwi[base + f4 * 4] = hp;
            float dv = dpart;
            #pragma unroll
            for (int s = 1; s < 16; s <<= 1) dv += __shfl_xor_sync(0xffffffffu, dv, s, 16);
            if ((tid & 15) == 0) sm[O_DIAG + t] = dv;
        }
    }
    __syncthreads();

    const int jh = wid >> 3;
    const int widL = wid & 7;
    const int blk = (widL < 4) ? widL : 11 - widL;
    const int i0 = blk * 16;
    int ntmax = (i0 + 16 - jh * 64) >> 3;
    ntmax = ntmax < 0 ? 0 : (ntmax > 8 ? 8 : ntmax);

    // ---- MMA1 (tf32): a strips ----
    float c1[8][4];
    #pragma unroll
    for (int nt = 0; nt < 8; ++nt)
        #pragma unroll
        for (int e = 0; e < 4; ++e) c1[nt][e] = 0.f;

    #pragma unroll
    for (int ks = 0; ks < 8; ++ks) {
        int k0 = ks * 8;
        const float* ar = &sm[O_RW + (i0 + ly) * 68 + k0 + lx];
        uint32_t a0 = FB(ar[0]), a1 = FB(ar[8 * 68]), a2 = FB(ar[4]), a3 = FB(ar[8 * 68 + 4]);
        #pragma unroll
        for (int nt = 0; nt < 8; ++nt) {
            if (nt < ntmax) {
                const float* br = &sm[O_KK + (jh * 64 + nt * 8 + ly) * 76 + k0 + lx];
                mma1688(c1[nt], a0, a1, a2, a3, FB(br[0]), FB(br[4]));
            }
        }
    }

    // ---- MMA3 (f16): wkv = kw^T @ v ----
    {
        const int i0k = (wid & 3) * 16, j3 = (wid >> 2) * 16;
        const uint32_t kwb = smem_u32(kwh);
        const uint32_t vhb = smem_u32(vh);
        float c3[2][4];
        #pragma unroll
        for (int g = 0; g < 2; ++g)
            #pragma unroll
            for (int e = 0; e < 4; ++e) c3[g][e] = 0.f;

        const int arow_off = (lid & 7) + ((lid >> 4) & 1) * 8;
        const int acol_off = ((lid >> 3) & 1) * 8;
        const int brow_off = (lid & 15);
        #pragma unroll
        for (int ksq = 0; ksq < 8; ++ksq) {
            int t0 = ksq * 16;
            uint32_t aaddr = kwb + (uint32_t)((t0 + arow_off) * 72 + i0k + acol_off) * 2;
            uint32_t a0, a1, a2, a3;
            ldmx4t(a0, a1, a2, a3, aaddr);
            uint32_t baddr = vhb + (uint32_t)((t0 + brow_off) * 72) * 2;
            uint32_t b0, b1;
            ldmx2t(b0, b1, baddr + j3 * 2);
            mma16816h(c3[0], a0, a1, a2, a3, b0, b1);
            uint32_t b2, b3;
            ldmx2t(b2, b3, baddr + (j3 + 8) * 2);
            mma16816h(c3[1], a0, a1, a2, a3, b2, b3);
        }
        int wb = bhn * (K_ * K_);
        int ilk = i0k + ly, ihk = ilk + 8;
        #pragma unroll
        for (int g = 0; g < 2; ++g) {
            int jb = j3 + g * 8 + 2 * lx;
            *(float2*)&g_wkv[wb + ilk * 64 + jb] = make_float2(c3[g][0], c3[g][1]);
            *(float2*)&g_wkv[wb + ihk * 64 + jb] = make_float2(c3[g][2], c3[g][3]);
        }
    }
    __syncthreads();

    // ---- MMA2 (f16): mask+pack A from c1, ldmatrix B from fp16 V ----
    float c2[8][4];
    #pragma unroll
    for (int nt = 0; nt < 8; ++nt)
        #pragma unroll
        for (int e = 0; e < 4; ++e) c2[nt][e] = 0.f;

    {
        const int il = i0 + ly, ih = il + 8;
        const uint32_t vhb = smem_u32(vh);
        const int ntp = ntmax >> 1;
        #pragma unroll
        for (int p = 0; p < 8; ++p) {
            if (p < ntp) {
                int nt0 = 2 * p, nt1 = nt0 + 1;
                int jc16 = jh * 64 + p * 16;
                int jcg0 = jc16 + 2 * lx;
                int jcg1 = jc16 + 8 + 2 * lx;
                uint32_t a0 = packh2((jcg0     < il) ? c1[nt0][0] : 0.f,
                                     (jcg0 + 1 < il) ? c1[nt0][1] : 0.f);
                uint32_t a1 = packh2((jcg0     < ih) ? c1[nt0][2] : 0.f,
                                     (jcg0 + 1 < ih) ? c1[nt0][3] : 0.f);
                uint32_t a2 = packh2((jcg1     < il) ? c1[nt1][0] : 0.f,
                                     (jcg1 + 1 < il) ? c1[nt1][1] : 0.f);
                uint32_t a3 = packh2((jcg1     < ih) ? c1[nt1][2] : 0.f,
                                     (jcg1 + 1 < ih) ? c1[nt1][3] : 0.f);
                uint32_t rowaddr = vhb + (uint32_t)(jc16 + (lid & 15)) * 144u;
                #pragma unroll
                for (int no = 0; no < 8; ++no) {
                    uint32_t b0, b1;
                    ldmx2t(b0, b1, rowaddr + no * 16);
                    mma16816h(c2[no], a0, a1, a2, a3, b0, b1);
                }
            }
        }
    }

    if (jh == 1 && ntmax > 0) {
        float* pb = &sm[O_RW + (blk - 4) * 1088];
        int jb = 2 * lx;
        #pragma unroll
        for (int nt = 0; nt < 8; ++nt) {
            *(float2*)&pb[ly * 68 + nt * 8 + jb]       = make_float2(c2[nt][0], c2[nt][1]);
            *(float2*)&pb[(ly + 8) * 68 + nt * 8 + jb] = make_float2(c2[nt][2], c2[nt][3]);
        }
    }
    __syncthreads();

    if (jh == 0) {
        const int il = i0 + ly, ih = il + 8;
        const float dgl = sm[O_DIAG + il], dgh = sm[O_DIAG + ih];
        const bool haveP = (blk >= 4);
        const float* pb = &sm[O_RW + (blk - 4) * 1088];
        #pragma unroll
        for (int nt = 0; nt < 8; ++nt) {
            int jb = nt * 8 + 2 * lx;
            float2 pl = make_float2(0.f, 0.f), ph = make_float2(0.f, 0.f);
            if (haveP) {
                pl = *(const float2*)&pb[ly * 68 + jb];
                ph = *(const float2*)&pb[(ly + 8) * 68 + jb];
            }
            float2 vl = *(const float2*)&sm[O_V + il * 72 + jb];
            float2 vh2 = *(const float2*)&sm[O_V + ih * 72 + jb];
            float o0 = c2[nt][0] + pl.x + dgl * vl.x;
            float o1 = c2[nt][1] + pl.y + dgl * vl.y;
            float o2 = c2[nt][2] + ph.x + dgh * vh2.x;
            float o3 = c2[nt][3] + ph.y + dgh * vh2.y;
            *(uint32_t*)&g_intra[base + il * 64 + jb] = packh2(o0, o1);
            *(uint32_t*)&g_intra[base + ih * 64 + jb] = packh2(o2, o3);
        }
    }
}

// ============ scan v5: fp16 rw cp.async, f16 MMA, fp16 intra + single out write ============
#define H_RW0  0
#define H_RW1  9216
#define H_ST0  18432
#define H_ST1  19584
#define SCAN_HALVES 20736
#define SCAN_BYTES  (SCAN_HALVES*2)

__global__ void __launch_bounds__(512)
rwkv_scan_inter(const float* __restrict__ state0, float* __restrict__ out,
                float* __restrict__ outF)
{
    extern __shared__ __half smh[];
    const int tid = threadIdx.x;
    const int wid = tid >> 5, lid = tid & 31;
    const int ly = lid >> 2, lx = lid & 3;
    const int bh = blockIdx.x >> 2;
    const int j0c = (blockIdx.x & 3) * 16;
    const int base_bh = bh * (T_ * K_);

    const uint32_t smb = smem_u32(smh);

    const int kq = tid >> 3;
    const int jq = (tid & 7) * 2;
    float2 st = *(const float2*)&state0[bh * (K_ * K_) + kq * 64 + j0c + jq];

    {
        const __half* src = g_rwi + base_bh;
        #pragma unroll
        for (int it = 0; it < 2; ++it) {
            int idx = tid + it * 512;
            int t = idx >> 3, g = idx & 7;
            cp_async16(smb + (H_RW0 + t * 72 + g * 8) * 2, src + t * 64 + g * 8);
        }
        cp_commit();
        smh[H_ST0 + jq * 72 + kq]       = __float2half(st.x);
        smh[H_ST0 + (jq + 1) * 72 + kq] = __float2half(st.y);
        cp_wait0();
    }
    __syncthreads();

    const int i0 = (wid & 7) * 16;
    const int jn = (wid >> 3) * 8;

    for (int n = 0; n < N_; ++n) {
        const int cur  = (n & 1) ? H_RW1 : H_RW0;
        const int curS = (n & 1) ? H_ST1 : H_ST0;
        const int nxt  = (n & 1) ? H_RW0 : H_RW1;
        const int nxtS = (n & 1) ? H_ST0 : H_ST1;

        if (n < 15) {
            const __half* src = g_rwi + base_bh + (n + 1) * (CH_ * K_);
            #pragma unroll
            for (int it = 0; it < 2; ++it) {
                int idx = tid + it * 512;
                int t = idx >> 3, g = idx & 7;
                cp_async16(smb + (nxt + t * 72 + g * 8) * 2, src + t * 64 + g * 8);
            }
            cp_commit();
        }

        const int cb = bh * N_ + n;
        float2 wkvv = *(const float2*)&g_wkv[cb * (K_ * K_) + kq * 64 + j0c + jq];
        float ews = __ldg(&g_wse[cb * K_ + kq]);

        // prefetch fp16 intra tile (no RMW of out)
        const int coff = n * (CH_ * K_);
        const int il = i0 + ly, ih = il + 8;
        const int jb = j0c + jn + 2 * lx;
        uint32_t i_l = *(const uint32_t*)&g_intra[base_bh + coff + il * 64 + jb];
        uint32_t i_h = *(const uint32_t*)&g_intra[base_bh + coff + ih * 64 + jb];

        float c[4] = {0.f, 0.f, 0.f, 0.f};
        #pragma unroll
        for (int ksq = 0; ksq < 4; ++ksq) {
            int k0 = ksq * 16;
            const __half* ar = &smh[cur + (i0 + ly) * 72 + k0 + 2 * lx];
            uint32_t a0 = *(const uint32_t*)ar;
            uint32_t a1 = *(const uint32_t*)(ar + 8 * 72);
            uint32_t a2 = *(const uint32_t*)(ar + 8);
            uint32_t a3 = *(const uint32_t*)(ar + 8 * 72 + 8);
            const __half* br = &smh[curS + (jn + ly) * 72 + k0 + 2 * lx];
            uint32_t b0 = *(const uint32_t*)br;
            uint32_t b1 = *(const uint32_t*)(br + 8);
            mma16816h(c, a0, a1, a2, a3, b0, b1);
        }

        float2 f_l = __half22float2(*(__half2*)&i_l);
        float2 f_h = __half22float2(*(__half2*)&i_h);
        float* ob = out + base_bh + coff;
        *(float2*)&ob[il * 64 + jb] = make_float2(f_l.x + c[0], f_l.y + c[1]);
        *(float2*)&ob[ih * 64 + jb] = make_float2(f_h.x + c[2], f_h.y + c[3]);

        st.x = fmaf(st.x, ews, wkvv.x);
        st.y = fmaf(st.y, ews, wkvv.y);

        if (n < 15) {
            smh[nxtS + jq * 72 + kq]       = __float2half(st.x);
            smh[nxtS + (jq + 1) * 72 + kq] = __float2half(st.y);
            cp_wait0();
            __syncthreads();
        }
    }

    *(float2*)&outF[bh * (K_ * K_) + kq * 64 + j0c + jq] = st;
}

extern "C" void kernel_launch(void* const* d_in, const int* in_sizes, int n_in,
                              void* d_out, int out_size)
{
    (void)in_sizes; (void)n_in; (void)out_size;
    const float* r  = (const float*)d_in[0];
    const float* k  = (const float*)d_in[1];
    const float* v  = (const float*)d_in[2];
    const float* w  = (const float*)d_in[3];
    const float* u  = (const float*)d_in[4];
    const float* s0 = (const float*)d_in[5];
    float* out  = (float*)d_out;
    float* outF = out + OUT_ELEMS;

    cudaFuncSetAttribute(rwkv_phase1, cudaFuncAttributeMaxDynamicSharedMemorySize, SMEM1_BYTES);
    cudaFuncSetAttribute(rwkv_scan_inter, cudaFuncAttributeMaxDynamicSharedMemorySize, SCAN_BYTES);

    rwkv_phase1<<<BH_ * N_, 512, SMEM1_BYTES>>>(r, k, v, w, u);
    rwkv_scan_inter<<<BH_ * 4, 512, SCAN_BYTES>>>(s0, out, outF);
}

// round 17
// speedup vs baseline: 1.0830x; 1.0830x over previous
#include <cuda_runtime.h>
#include <cuda_fp16.h>
#include <cstdint>

#define B_ 4
#define H_ 16
#define T_ 2048
#define K_ 64
#define CH_ 128
#define N_ 16
#define BH_ (B_*H_)
#define OUT_ELEMS (B_*H_*T_*K_)
#define LOGMIN (-5.2983174324035645f)

// ---- scratch ----
__device__ __half g_rwi[B_*H_*T_*K_];     // r * exp(cum_prev)  (fp16)
__device__ float g_wkv[BH_*N_*K_*K_];
__device__ float g_wse[BH_*N_*K_];

// ---- phase1 smem layout (float offsets) ----
#define O_RW    0        // 128 x 68 (8704); later partial buffers
#define O_CUM   8704     // 128 x 64 (8192)
#define O_KK    16896    // 128 x 76 (9728) tf32 kk (MMA1 only)
#define O_U     26624
#define O_DIAG  26688    // 128
#define O_EWS   26816    // 64
#define O_SEG   26880    // 8 x 64
#define O_VH    27392    // fp16 V: 128 x 72 halves (4608 floats)
#define O_KW    32000    // fp16 kw: 128 x 72 halves (4608 floats)
#define SMEM1_FLOATS 36608
#define SMEM1_BYTES  (SMEM1_FLOATS*4)

__device__ __forceinline__ float f2tf(float x) {
    uint32_t r;
    asm("cvt.rna.tf32.f32 %0, %1;" : "=r"(r) : "f"(x));
    return __uint_as_float(r);
}
__device__ __forceinline__ uint32_t packh2(float a, float b) {
    __half2 h = __floats2half2_rn(a, b);
    return *(uint32_t*)&h;
}
__device__ __forceinline__ void mma1688(float* c, uint32_t a0, uint32_t a1, uint32_t a2, uint32_t a3,
                                        uint32_t b0, uint32_t b1) {
    asm volatile("mma.sync.aligned.m16n8k8.row.col.f32.tf32.tf32.f32 "
                 "{%0,%1,%2,%3},{%4,%5,%6,%7},{%8,%9},{%0,%1,%2,%3};"
                 : "+f"(c[0]), "+f"(c[1]), "+f"(c[2]), "+f"(c[3])
                 : "r"(a0), "r"(a1), "r"(a2), "r"(a3), "r"(b0), "r"(b1));
}
__device__ __forceinline__ void mma16816h(float* c, uint32_t a0, uint32_t a1, uint32_t a2, uint32_t a3,
                                          uint32_t b0, uint32_t b1) {
    asm volatile("mma.sync.aligned.m16n8k16.row.col.f32.f16.f16.f32 "
                 "{%0,%1,%2,%3},{%4,%5,%6,%7},{%8,%9},{%0,%1,%2,%3};"
                 : "+f"(c[0]), "+f"(c[1]), "+f"(c[2]), "+f"(c[3])
                 : "r"(a0), "r"(a1), "r"(a2), "r"(a3), "r"(b0), "r"(b1));
}
__device__ __forceinline__ void ldmx2t(uint32_t& b0, uint32_t& b1, uint32_t addr) {
    asm volatile("ldmatrix.sync.aligned.m8n8.x2.trans.shared.b16 {%0,%1}, [%2];"
                 : "=r"(b0), "=r"(b1) : "r"(addr));
}
__device__ __forceinline__ void ldmx4t(uint32_t& r0, uint32_t& r1, uint32_t& r2, uint32_t& r3,
                                       uint32_t addr) {
    asm volatile("ldmatrix.sync.aligned.m8n8.x4.trans.shared.b16 {%0,%1,%2,%3}, [%4];"
                 : "=r"(r0), "=r"(r1), "=r"(r2), "=r"(r3) : "r"(addr));
}
#define FB(x) __float_as_uint(x)

__device__ __forceinline__ uint32_t smem_u32(const void* p) {
    uint32_t a;
    asm("{ .reg .u64 t; cvta.to.shared.u64 t, %1; cvt.u32.u64 %0, t; }" : "=r"(a) : "l"(p));
    return a;
}
__device__ __forceinline__ void cp_async16(uint32_t dst, const void* src) {
    asm volatile("cp.async.cg.shared.global [%0], [%1], 16;" :: "r"(dst), "l"(src) : "memory");
}
__device__ __forceinline__ void cp_commit() { asm volatile("cp.async.commit_group;" ::: "memory"); }
__device__ __forceinline__ void cp_wait0()  { asm volatile("cp.async.wait_group 0;" ::: "memory"); }

// ======================= phase 1 =======================
__global__ void __launch_bounds__(512)
rwkv_phase1(const float* __restrict__ r, const float* __restrict__ k,
            const float* __restrict__ v, const float* __restrict__ w,
            const float* __restrict__ u, float* __restrict__ out)
{
    extern __shared__ float sm[];
    __half* vh  = (__half*)(sm + O_VH);
    __half* kwh = (__half*)(sm + O_KW);
    const int tid = threadIdx.x;
    const int wid = tid >> 5, lid = tid & 31;
    const int ly = lid >> 2, lx = lid & 3;
    const int bhn = blockIdx.x;
    const int bh = bhn >> 4, n = bhn & 15;
    const int h = bh & (H_ - 1);
    const int base = bh * (T_ * K_) + n * (CH_ * K_);

    float4 pr[4], pk[4];
    {
        const float4* r4g = (const float4*)(r + base);
        const float4* k4g = (const float4*)(k + base);
        #pragma unroll
        for (int it = 0; it < 4; ++it) {
            pr[it] = r4g[tid + it * 512];
            pk[it] = k4g[tid + it * 512];
        }
    }

    {
        const float4* w4 = (const float4*)(w + base);
        const float4* v4 = (const float4*)(v + base);
        #pragma unroll
        for (int it = 0; it < 4; ++it) {
            int f4 = tid + it * 512;
            int t = f4 >> 4, k0 = (f4 & 15) * 4;
            float4 ww = w4[f4];
            ww.x = fmaxf(ww.x, LOGMIN); ww.y = fmaxf(ww.y, LOGMIN);
            ww.z = fmaxf(ww.z, LOGMIN); ww.w = fmaxf(ww.w, LOGMIN);
            *(float4*)&sm[O_CUM + t * 64 + k0] = ww;
            float4 vv = v4[f4];
            vv.x = f2tf(vv.x); vv.y = f2tf(vv.y); vv.z = f2tf(vv.z); vv.w = f2tf(vv.w);
            uint2 hp = make_uint2(packh2(vv.x, vv.y), packh2(vv.z, vv.w));
            *(uint2*)&vh[t * 72 + k0] = hp;
        }
        if (tid < 64) sm[O_U + tid] = u[h * 64 + tid];
    }
    __syncthreads();

    {
        int kq = tid & 63, seg = tid >> 6;
        float run = 0.f;
        #pragma unroll
        for (int tt = 0; tt < 16; ++tt) {
            int idx = (seg * 16 + tt) * 64 + kq;
            run += sm[O_CUM + idx];
            sm[O_CUM + idx] = run;
        }
        sm[O_SEG + seg * 64 + kq] = run;
    }
    __syncthreads();

    {
        int kq = tid & 63, seg = tid >> 6;
        if (seg > 0) {
            float pre = 0.f;
            #pragma unroll
            for (int s = 0; s < 7; ++s)
                if (s < seg) pre += sm[O_SEG + s * 64 + kq];
            #pragma unroll
            for (int tt = 0; tt < 16; ++tt) sm[O_CUM + (seg * 16 + tt) * 64 + kq] += pre;
        } else {
            float ws = 0.f;
            #pragma unroll
            for (int s = 0; s < 8; ++s) ws += sm[O_SEG + s * 64 + kq];
            float ews = __expf(ws);
            sm[O_EWS + kq] = ews;
            g_wse[(bh * N_ + n) * K_ + kq] = ews;
        }
    }
    __syncthreads();

    {
        #pragma unroll
        for (int it = 0; it < 4; ++it) {
            int f4 = tid + it * 512;
            int t = f4 >> 4, k0 = (f4 & 15) * 4;
            float4 rv = pr[it];
            float4 kv = pk[it];
            float4 c4 = *(const float4*)&sm[O_CUM + t * 64 + k0];
            float4 cp4 = (t > 0) ? *(const float4*)&sm[O_CUM + (t - 1) * 64 + k0]
                                 : make_float4(0.f, 0.f, 0.f, 0.f);
            float4 uu = *(const float4*)&sm[O_U + k0];
            float4 ew4 = *(const float4*)&sm[O_EWS + k0];
            float re[4] = {rv.x, rv.y, rv.z, rv.w};
            float ke[4] = {kv.x, kv.y, kv.z, kv.w};
            float ce[4] = {c4.x, c4.y, c4.z, c4.w};
            float cpe[4] = {cp4.x, cp4.y, cp4.z, cp4.w};
            float ue[4] = {uu.x, uu.y, uu.z, uu.w};
            float ewe[4] = {ew4.x, ew4.y, ew4.z, ew4.w};
            float rwv[4], kkv[4], kwv[4];
            float dpart = 0.f;
            #pragma unroll
            for (int e = 0; e < 4; ++e) {
                rwv[e] = f2tf(re[e] * __expf(cpe[e]));   // r * exp(cum_prev)
                kkv[e] = f2tf(ke[e] * __expf(-ce[e]));   // k * exp(-cum)
                kwv[e] = kkv[e] * ewe[e];                // k * exp(ws - cum), bounded
                dpart += re[e] * ue[e] * ke[e];
            }
            *(float4*)&sm[O_RW + t * 68 + k0] = make_float4(rwv[0], rwv[1], rwv[2], rwv[3]);
            *(float4*)&sm[O_KK + t * 76 + k0] = make_float4(kkv[0], kkv[1], kkv[2], kkv[3]);
            uint2 kwp = make_uint2(packh2(kwv[0], kwv[1]), packh2(kwv[2], kwv[3]));
            *(uint2*)&kwh[t * 72 + k0] = kwp;
            uint2 hp = make_uint2(packh2(rwv[0], rwv[1]), packh2(rwv[2], rwv[3]));
            *(uint2*)&g_rwi[base + f4 * 4] = hp;
            float dv = dpart;
            #pragma unroll
            for (int s = 1; s < 16; s <<= 1) dv += __shfl_xor_sync(0xffffffffu, dv, s, 16);
            if ((tid & 15) == 0) sm[O_DIAG + t] = dv;
        }
    }
    __syncthreads();

    const int jh = wid >> 3;
    const int widL = wid & 7;
    const int blk = (widL < 4) ? widL : 11 - widL;
    const int i0 = blk * 16;
    int ntmax = (i0 + 16 - jh * 64) >> 3;
    ntmax = ntmax < 0 ? 0 : (ntmax > 8 ? 8 : ntmax);

    // ---- MMA1 (tf32): a strips ----
    float c1[8][4];
    #pragma unroll
    for (int nt = 0; nt < 8; ++nt)
        #pragma unroll
        for (int e = 0; e < 4; ++e) c1[nt][e] = 0.f;

    #pragma unroll
    for (int ks = 0; ks < 8; ++ks) {
        int k0 = ks * 8;
        const float* ar = &sm[O_RW + (i0 + ly) * 68 + k0 + lx];
        uint32_t a0 = FB(ar[0]), a1 = FB(ar[8 * 68]), a2 = FB(ar[4]), a3 = FB(ar[8 * 68 + 4]);
        #pragma unroll
        for (int nt = 0; nt < 8; ++nt) {
            if (nt < ntmax) {
                const float* br = &sm[O_KK + (jh * 64 + nt * 8 + ly) * 76 + k0 + lx];
                mma1688(c1[nt], a0, a1, a2, a3, FB(br[0]), FB(br[4]));
            }
        }
    }

    // ---- MMA3 (f16): wkv = kw^T @ v ----
    {
        const int i0k = (wid & 3) * 16, j3 = (wid >> 2) * 16;
        const uint32_t kwb = smem_u32(kwh);
        const uint32_t vhb = smem_u32(vh);
        float c3[2][4];
        #pragma unroll
        for (int g = 0; g < 2; ++g)
            #pragma unroll
            for (int e = 0; e < 4; ++e) c3[g][e] = 0.f;

        const int arow_off = (lid & 7) + ((lid >> 4) & 1) * 8;
        const int acol_off = ((lid >> 3) & 1) * 8;
        const int brow_off = (lid & 15);
        #pragma unroll
        for (int ksq = 0; ksq < 8; ++ksq) {
            int t0 = ksq * 16;
            uint32_t aaddr = kwb + (uint32_t)((t0 + arow_off) * 72 + i0k + acol_off) * 2;
            uint32_t a0, a1, a2, a3;
            ldmx4t(a0, a1, a2, a3, aaddr);
            uint32_t baddr = vhb + (uint32_t)((t0 + brow_off) * 72) * 2;
            uint32_t b0, b1;
            ldmx2t(b0, b1, baddr + j3 * 2);
            mma16816h(c3[0], a0, a1, a2, a3, b0, b1);
            uint32_t b2, b3;
            ldmx2t(b2, b3, baddr + (j3 + 8) * 2);
            mma16816h(c3[1], a0, a1, a2, a3, b2, b3);
        }
        int wb = bhn * (K_ * K_);
        int ilk = i0k + ly, ihk = ilk + 8;
        #pragma unroll
        for (int g = 0; g < 2; ++g) {
            int jb = j3 + g * 8 + 2 * lx;
            *(float2*)&g_wkv[wb + ilk * 64 + jb] = make_float2(c3[g][0], c3[g][1]);
            *(float2*)&g_wkv[wb + ihk * 64 + jb] = make_float2(c3[g][2], c3[g][3]);
        }
    }
    __syncthreads();

    // ---- MMA2 (f16): mask+pack A from c1, ldmatrix B from fp16 V ----
    float c2[8][4];
    #pragma unroll
    for (int nt = 0; nt < 8; ++nt)
        #pragma unroll
        for (int e = 0; e < 4; ++e) c2[nt][e] = 0.f;

    {
        const int il = i0 + ly, ih = il + 8;
        const uint32_t vhb = smem_u32(vh);
        const int ntp = ntmax >> 1;
        #pragma unroll
        for (int p = 0; p < 8; ++p) {
            if (p < ntp) {
                int nt0 = 2 * p, nt1 = nt0 + 1;
                int jc16 = jh * 64 + p * 16;
                int jcg0 = jc16 + 2 * lx;
                int jcg1 = jc16 + 8 + 2 * lx;
                uint32_t a0 = packh2((jcg0     < il) ? c1[nt0][0] : 0.f,
                                     (jcg0 + 1 < il) ? c1[nt0][1] : 0.f);
                uint32_t a1 = packh2((jcg0     < ih) ? c1[nt0][2] : 0.f,
                                     (jcg0 + 1 < ih) ? c1[nt0][3] : 0.f);
                uint32_t a2 = packh2((jcg1     < il) ? c1[nt1][0] : 0.f,
                                     (jcg1 + 1 < il) ? c1[nt1][1] : 0.f);
                uint32_t a3 = packh2((jcg1     < ih) ? c1[nt1][2] : 0.f,
                                     (jcg1 + 1 < ih) ? c1[nt1][3] : 0.f);
                uint32_t rowaddr = vhb + (uint32_t)(jc16 + (lid & 15)) * 144u;
                #pragma unroll
                for (int no = 0; no < 8; ++no) {
                    uint32_t b0, b1;
                    ldmx2t(b0, b1, rowaddr + no * 16);
                    mma16816h(c2[no], a0, a1, a2, a3, b0, b1);
                }
            }
        }
    }

    if (jh == 1 && ntmax > 0) {
        float* pb = &sm[O_RW + (blk - 4) * 1088];
        int jb = 2 * lx;
        #pragma unroll
        for (int nt = 0; nt < 8; ++nt) {
            *(float2*)&pb[ly * 68 + nt * 8 + jb]       = make_float2(c2[nt][0], c2[nt][1]);
            *(float2*)&pb[(ly + 8) * 68 + nt * 8 + jb] = make_float2(c2[nt][2], c2[nt][3]);
        }
    }
    __syncthreads();

    if (jh == 0) {
        const int il = i0 + ly, ih = il + 8;
        const float dgl = sm[O_DIAG + il], dgh = sm[O_DIAG + ih];
        const bool haveP = (blk >= 4);
        const float* pb = &sm[O_RW + (blk - 4) * 1088];
        #pragma unroll
        for (int nt = 0; nt < 8; ++nt) {
            int jb = nt * 8 + 2 * lx;
            float2 pl = make_float2(0.f, 0.f), ph = make_float2(0.f, 0.f);
            if (haveP) {
                pl = *(const float2*)&pb[ly * 68 + jb];
                ph = *(const float2*)&pb[(ly + 8) * 68 + jb];
            }
            uint32_t vlp = *(const uint32_t*)&vh[il * 72 + jb];
            uint32_t vhp = *(const uint32_t*)&vh[ih * 72 + jb];
            float2 vl = __half22float2(*(__half2*)&vlp);
            float2 vh2 = __half22float2(*(__half2*)&vhp);
            float o0 = c2[nt][0] + pl.x + dgl * vl.x;
            float o1 = c2[nt][1] + pl.y + dgl * vl.y;
            float o2 = c2[nt][2] + ph.x + dgh * vh2.x;
            float o3 = c2[nt][3] + ph.y + dgh * vh2.y;
            *(float2*)&out[base + il * 64 + jb] = make_float2(o0, o1);
            *(float2*)&out[base + ih * 64 + jb] = make_float2(o2, o3);
        }
    }
}

// ============ scan v4 (round-15 best): fp16 rw cp.async + f16 MMA + fp32 out RMW ============
#define H_RW0  0
#define H_RW1  9216
#define H_ST0  18432
#define H_ST1  19584
#define SCAN_HALVES 20736
#define SCAN_BYTES  (SCAN_HALVES*2)

__global__ void __launch_bounds__(512)
rwkv_scan_inter(const float* __restrict__ state0, float* __restrict__ out,
                float* __restrict__ outF)
{
    extern __shared__ __half smh[];
    const int tid = threadIdx.x;
    const int wid = tid >> 5, lid = tid & 31;
    const int ly = lid >> 2, lx = lid & 3;
    const int bh = blockIdx.x >> 2;
    const int j0c = (blockIdx.x & 3) * 16;
    const int base_bh = bh * (T_ * K_);

    const uint32_t smb = smem_u32(smh);

    const int kq = tid >> 3;
    const int jq = (tid & 7) * 2;
    float2 st = *(const float2*)&state0[bh * (K_ * K_) + kq * 64 + j0c + jq];

    {
        const __half* src = g_rwi + base_bh;
        #pragma unroll
        for (int it = 0; it < 2; ++it) {
            int idx = tid + it * 512;
            int t = idx >> 3, g = idx & 7;
            cp_async16(smb + (H_RW0 + t * 72 + g * 8) * 2, src + t * 64 + g * 8);
        }
        cp_commit();
        smh[H_ST0 + jq * 72 + kq]       = __float2half(st.x);
        smh[H_ST0 + (jq + 1) * 72 + kq] = __float2half(st.y);
        cp_wait0();
    }
    __syncthreads();

    const int i0 = (wid & 7) * 16;
    const int jn = (wid >> 3) * 8;

    for (int n = 0; n < N_; ++n) {
        const int cur  = (n & 1) ? H_RW1 : H_RW0;
        const int curS = (n & 1) ? H_ST1 : H_ST0;
        const int nxt  = (n & 1) ? H_RW0 : H_RW1;
        const int nxtS = (n & 1) ? H_ST0 : H_ST1;

        if (n < 15) {
            const __half* src = g_rwi + base_bh + (n + 1) * (CH_ * K_);
            #pragma unroll
            for (int it = 0; it < 2; ++it) {
                int idx = tid + it * 512;
                int t = idx >> 3, g = idx & 7;
                cp_async16(smb + (nxt + t * 72 + g * 8) * 2, src + t * 64 + g * 8);
            }
            cp_commit();
        }

        const int cb = bh * N_ + n;
        float2 wkvv = *(const float2*)&g_wkv[cb * (K_ * K_) + kq * 64 + j0c + jq];
        float ews = __ldg(&g_wse[cb * K_ + kq]);

        float* ob = out + base_bh + n * (CH_ * K_);
        const int il = i0 + ly, ih = il + 8;
        const int jb = j0c + jn + 2 * lx;
        float2 o_l = *(const float2*)&ob[il * 64 + jb];
        float2 o_h = *(const float2*)&ob[ih * 64 + jb];

        float c[4] = {0.f, 0.f, 0.f, 0.f};
        #pragma unroll
        for (int ksq = 0; ksq < 4; ++ksq) {
            int k0 = ksq * 16;
            const __half* ar = &smh[cur + (i0 + ly) * 72 + k0 + 2 * lx];
            uint32_t a0 = *(const uint32_t*)ar;
            uint32_t a1 = *(const uint32_t*)(ar + 8 * 72);
            uint32_t a2 = *(const uint32_t*)(ar + 8);
            uint32_t a3 = *(const uint32_t*)(ar + 8 * 72 + 8);
            const __half* br = &smh[curS + (jn + ly) * 72 + k0 + 2 * lx];
            uint32_t b0 = *(const uint32_t*)br;
            uint32_t b1 = *(const uint32_t*)(br + 8);
            mma16816h(c, a0, a1, a2, a3, b0, b1);
        }

        o_l.x += c[0]; o_l.y += c[1];
        o_h.x += c[2]; o_h.y += c[3];
        *(float2*)&ob[il * 64 + jb] = o_l;
        *(float2*)&ob[ih * 64 + jb] = o_h;

        st.x = fmaf(st.x, ews, wkvv.x);
        st.y = fmaf(st.y, ews, wkvv.y);

        if (n < 15) {
            smh[nxtS + jq * 72 + kq]       = __float2half(st.x);
            smh[nxtS + (jq + 1) * 72 + kq] = __float2half(st.y);
            cp_wait0();
            __syncthreads();
        }
    }

    *(float2*)&outF[bh * (K_ * K_) + kq * 64 + j0c + jq] = st;
}

extern "C" void kernel_launch(void* const* d_in, const int* in_sizes, int n_in,
                              void* d_out, int out_size)
{
    (void)in_sizes; (void)n_in; (void)out_size;
    const float* r  = (const float*)d_in[0];
    const float* k  = (const float*)d_in[1];
    const float* v  = (const float*)d_in[2];
    const float* w  = (const float*)d_in[3];
    const float* u  = (const float*)d_in[4];
    const float* s0 = (const float*)d_in[5];
    float* out  = (float*)d_out;
    float* outF = out + OUT_ELEMS;

    cudaFuncSetAttribute(rwkv_phase1, cudaFuncAttributeMaxDynamicSharedMemorySize, SMEM1_BYTES);
    cudaFuncSetAttribute(rwkv_scan_inter, cudaFuncAttributeMaxDynamicSharedMemorySize, SCAN_BYTES);

    rwkv_phase1<<<BH_ * N_, 512, SMEM1_BYTES>>>(r, k, v, w, u, out);
    rwkv_scan_inter<<<BH_ * 4, 512, SCAN_BYTES>>>(s0, out, outF);
}